// round 13
// baseline (speedup 1.0000x reference)
#include <cuda_runtime.h>
#include <cuda_bf16.h>
#include <math.h>
#include <stdint.h>

#define B_  32
#define T_  256
#define D_  1024
#define M_  256
#define S_  64
#define ROWS_ 2048
#define BT_  8192
#define ST  528               // smem tile row stride in bytes (264 bf16) — conflict-free frag loads

// ---------------- static device scratch ----------------
__device__ float g_mem[(size_t)ROWS_ * M_];      // raw (pre-norm) memory, in place
__device__ float g_ss[B_ * 4 * S_];              // sum-of-squares partials [b][p][s]
__device__ float g_usage[2][ROWS_];              // parity double-buffered usage
__device__ float g_ww[ROWS_];
__device__ __nv_bfloat16 g_rm_h[(size_t)ROWS_ * M_];
__device__ __nv_bfloat16 g_rm_l[(size_t)ROWS_ * M_];
__device__ float g_zg[(size_t)ROWS_ * M_];
__device__ float g_mv[(size_t)BT_ * 512];        // mem_input | vals
__device__ float g_vproj[(size_t)BT_ * 768];
__device__ float g_Wiv[(size_t)512 * D_];
__device__ float g_biv[512];
__device__ float g_Wx[(size_t)768 * M_];
__device__ __nv_bfloat16 g_Whh[(size_t)768 * M_];   // h-half weights bf16 hi [n][k]
__device__ __nv_bfloat16 g_Whl[(size_t)768 * M_];   // h-half weights bf16 lo
__device__ float g_bx[768];

__device__ __forceinline__ float sigm(float x) { return 1.f / (1.f + expf(-x)); }

__device__ __forceinline__ void hilo2(float x0, float x1, uint32_t& hw, uint32_t& lw)
{
    __nv_bfloat162 h, l;
    h.x = __float2bfloat16(x0); h.y = __float2bfloat16(x1);
    l.x = __float2bfloat16(x0 - __bfloat162float(h.x));
    l.y = __float2bfloat16(x1 - __bfloat162float(h.y));
    hw = *(uint32_t*)&h; lw = *(uint32_t*)&l;
}

// m16n8k16 row.col f32.bf16.bf16.f32 (baseline sm_80+ PTX — assembles for sm_100)
#define MMA(acc, a0,a1,a2,a3, b0,b1) \
    asm volatile("mma.sync.aligned.m16n8k16.row.col.f32.bf16.bf16.f32 " \
        "{%0,%1,%2,%3}, {%4,%5,%6,%7}, {%8,%9}, {%0,%1,%2,%3};" \
        : "+f"((acc)[0]), "+f"((acc)[1]), "+f"((acc)[2]), "+f"((acc)[3]) \
        : "r"(a0), "r"(a1), "r"(a2), "r"(a3), "r"(b0), "r"(b1))

// ---------------- pack ----------------
__global__ void k_pack(const float* __restrict__ Wi, const float* __restrict__ bi,
                       const float* __restrict__ Wv, const float* __restrict__ bv,
                       const float* __restrict__ Wr, const float* __restrict__ br,
                       const float* __restrict__ Wz, const float* __restrict__ bz,
                       const float* __restrict__ Wu, const float* __restrict__ bu)
{
    int idx = blockIdx.x * blockDim.x + threadIdx.x;
    if (idx < 512 * 1024) {
        int r = idx >> 10, k = idx & 1023;
        g_Wiv[idx] = (r < 256) ? Wi[r * 1024 + k] : Wv[(r - 256) * 1024 + k];
    }
    if (idx < 768 * 256) {
        int n = idx >> 8, k = idx & 255;
        int gate = n >> 8, jj = n & 255;
        const float* Wg = (gate == 0) ? Wr : ((gate == 1) ? Wz : Wu);
        g_Wx[idx] = Wg[jj * 512 + k];
        float w = Wg[jj * 512 + 256 + k];
        __nv_bfloat16 h = __float2bfloat16(w);
        g_Whh[idx] = h;
        g_Whl[idx] = __float2bfloat16(w - __bfloat162float(h));
    }
    if (idx < 768) g_bx[idx] = (idx < 256) ? br[idx] : ((idx < 512) ? bz[idx - 256] : bu[idx - 512]);
    if (idx < 512) g_biv[idx] = (idx < 256) ? bi[idx] : bv[idx - 256];
}

// ---------------- init ----------------
__global__ void k_init(const float* __restrict__ mi)
{
    int row = blockIdx.x, tid = threadIdx.x;
    float v = 0.01f * mi[(size_t)row * M_ + tid];
    g_mem[(size_t)row * M_ + tid] = v;
    float ss = v * v;
    #pragma unroll
    for (int off = 16; off; off >>= 1) ss += __shfl_xor_sync(0xffffffffu, ss, off);
    __shared__ float wsum[8];
    if ((tid & 31) == 0) wsum[tid >> 5] = ss;
    __syncthreads();
    if (tid < 4) {
        int b = row >> 6, s = row & 63;
        g_ss[(b * 4 + tid) * 64 + s] = wsum[2 * tid] + wsum[2 * tid + 1];
    }
    if (tid == 0) g_usage[0][row] = 0.f;
}

// ---------------- precompute GEMMs (fp32, unchanged from passing R9) ----------------
template<int KTILE>
__device__ __forceinline__ void gemm_tile(const float* __restrict__ A, int lda,
                                          const float* __restrict__ W, int ldw,
                                          int K, int row0, int n0, float acc[4][4])
{
    __shared__ __align__(16) float sA[KTILE][68];
    __shared__ __align__(16) float sW[KTILE][68];
    const int tid = threadIdx.x;
    const int lr = tid >> 2, lk = (tid & 3) * 4;
    const int ty = tid >> 4, tx = tid & 15;
    for (int k0 = 0; k0 < K; k0 += KTILE) {
        float4 av = *(const float4*)(A + (size_t)(row0 + lr) * lda + k0 + lk);
        float4 wv = *(const float4*)(W + (size_t)(n0 + lr) * ldw + k0 + lk);
        __syncthreads();
        sA[lk + 0][lr] = av.x; sA[lk + 1][lr] = av.y; sA[lk + 2][lr] = av.z; sA[lk + 3][lr] = av.w;
        sW[lk + 0][lr] = wv.x; sW[lk + 1][lr] = wv.y; sW[lk + 2][lr] = wv.z; sW[lk + 3][lr] = wv.w;
        __syncthreads();
        #pragma unroll
        for (int kk = 0; kk < KTILE; kk++) {
            float4 a = *(const float4*)&sA[kk][ty * 4];
            float4 w = *(const float4*)&sW[kk][tx * 4];
            float ar[4] = {a.x, a.y, a.z, a.w};
            float wr[4] = {w.x, w.y, w.z, w.w};
            #pragma unroll
            for (int i = 0; i < 4; i++)
                #pragma unroll
                for (int j = 0; j < 4; j++)
                    acc[i][j] = fmaf(ar[i], wr[j], acc[i][j]);
        }
    }
}

__global__ void k_gemm_pre(const float* __restrict__ hidden, int mode)
{
    const float* A; const float* W; const float* bias; float* C;
    int lda, ldw, ldc, K, ntn;
    if (mode == 0) { A = hidden;     lda = 1024; W = g_Wiv; ldw = 1024; bias = g_biv; C = g_mv;    ldc = 512; K = 1024; ntn = 8;  }
    else           { A = g_mv + 256; lda = 512;  W = g_Wx;  ldw = 256;  bias = g_bx;  C = g_vproj; ldc = 768; K = 256;  ntn = 12; }
    int tr = blockIdx.x / ntn, tc = blockIdx.x % ntn;
    int row0 = tr * 64, n0 = tc * 64;
    float acc[4][4] = {};
    gemm_tile<16>(A, lda, W, ldw, K, row0, n0, acc);
    int ty = threadIdx.x >> 4, tx = threadIdx.x & 15;
    #pragma unroll
    for (int i = 0; i < 4; i++) {
        int r = row0 + ty * 4 + i;
        #pragma unroll
        for (int j = 0; j < 4; j++) {
            int n = n0 + tx * 4 + j;
            C[(size_t)r * ldc + n] = acc[i][j] + bias[n];
        }
    }
}

// ---------------- shared HMMA core: 64 x (NT*8*2 cols) x K256, bf16-split 3-pass ----------------
template<int NT>
__device__ __forceinline__ void mma_gemm(const char* sm, uint32_t bhOff, uint32_t blOff,
                                         float acc[NT][4], int wr, int wc, int g, int q)
{
    const char* pAH = sm + (wr * 16 + g) * ST + q * 4;
    const char* pAL = pAH + 33792;
    const char* pBH = sm + bhOff + (wc * (NT * 8) + g) * ST + q * 4;
    const char* pBL = sm + blOff + (wc * (NT * 8) + g) * ST + q * 4;
    #pragma unroll 2
    for (int kc = 0; kc < 16; kc++) {
        const int kb = kc * 32;
        uint32_t ah0 = *(const uint32_t*)(pAH + kb);
        uint32_t ah1 = *(const uint32_t*)(pAH + kb + 8 * ST);
        uint32_t ah2 = *(const uint32_t*)(pAH + kb + 16);
        uint32_t ah3 = *(const uint32_t*)(pAH + kb + 8 * ST + 16);
        uint32_t al0 = *(const uint32_t*)(pAL + kb);
        uint32_t al1 = *(const uint32_t*)(pAL + kb + 8 * ST);
        uint32_t al2 = *(const uint32_t*)(pAL + kb + 16);
        uint32_t al3 = *(const uint32_t*)(pAL + kb + 8 * ST + 16);
        #pragma unroll
        for (int nt = 0; nt < NT; nt++) {
            uint32_t bh0 = *(const uint32_t*)(pBH + nt * 8 * ST + kb);
            uint32_t bh1 = *(const uint32_t*)(pBH + nt * 8 * ST + kb + 16);
            uint32_t bl0 = *(const uint32_t*)(pBL + nt * 8 * ST + kb);
            uint32_t bl1 = *(const uint32_t*)(pBL + nt * 8 * ST + kb + 16);
            MMA(acc[nt], ah0, ah1, ah2, ah3, bh0, bh1);
            MMA(acc[nt], al0, al1, al2, al3, bh0, bh1);
            MMA(acc[nt], ah0, ah1, ah2, ah3, bl0, bl1);
        }
    }
}

// ---------------- step2: softmax(j0) + r,z HMMA GEMM (grid 32*4, N=128 each) ----------------
// smem: AH 0 (33792) | AL 33792 | BH 67584 (67584) | BL 135168 | X 202752: sScl 256B, sSco 256B, dvec 1024B
#define S2_X 202752
#define S2_SMEM (S2_X + 1536)
__global__ void __launch_bounds__(256) k_step2(int t)
{
    extern __shared__ __align__(16) char sm[];
    const int tid = threadIdx.x, wid = tid >> 5, lane = tid & 31;
    const int g = lane >> 2, q = lane & 3;
    const int b = blockIdx.x >> 2, j = blockIdx.x & 3;
    float* sScl = (float*)(sm + S2_X);
    float* sSco = (float*)(sm + S2_X + 256);
    float* dvec = (float*)(sm + S2_X + 512);

    if (tid < 64) {
        const float* ssB = g_ss + b * 256;
        float tot = ssB[tid] + ssB[64 + tid] + ssB[128 + tid] + ssB[192 + tid];
        sScl[tid] = 1.f / fmaxf(sqrtf(tot), 1e-12f);
    }
    __syncthreads();

    // A: mem_norm -> bf16 hi/lo (64 rows x 256)
    {
        int row = tid >> 2, ks = (tid & 3) * 64;
        float scl = sScl[row];
        const float* src = g_mem + (size_t)(b * 64 + row) * 256 + ks;
        char* dh = sm + row * ST + ks * 2;
        char* dl = dh + 33792;
        #pragma unroll
        for (int i = 0; i < 16; i++) {
            float4 f = __ldcg((const float4*)(src + i * 4));
            uint32_t h0, l0, h1, l1;
            hilo2(f.x * scl, f.y * scl, h0, l0);
            hilo2(f.z * scl, f.w * scl, h1, l1);
            *(uint32_t*)(dh + i * 8) = h0; *(uint32_t*)(dh + i * 8 + 4) = h1;
            *(uint32_t*)(dl + i * 8) = l0; *(uint32_t*)(dl + i * 8 + 4) = l1;
        }
    }
    // B: W_rz slice rows j*128 .. j*128+127 (bf16 hi/lo prepacked)
    {
        int row = tid >> 1, ks = (tid & 1) * 128;
        const char* shp = (const char*)g_Whh + ((size_t)(j * 128 + row) * 256 + ks) * 2;
        const char* slp = (const char*)g_Whl + ((size_t)(j * 128 + row) * 256 + ks) * 2;
        char* dh = sm + 67584 + row * ST + ks * 2;
        char* dl = sm + 135168 + row * ST + ks * 2;
        #pragma unroll
        for (int i = 0; i < 16; i++) {
            *(uint4*)(dh + i * 16) = __ldcg((const uint4*)(shp + i * 16));
            *(uint4*)(dl + i * 16) = __ldcg((const uint4*)(slp + i * 16));
        }
    }

    // j==0 CTA: sim + softmax + publish ww/usage (fp32, exact as before)
    if (j == 0) {
        dvec[tid] = g_mv[((size_t)(b * T_ + t)) * 512 + tid];
        __syncthreads();
        #pragma unroll
        for (int rr = 0; rr < 8; rr++) {
            int s = wid * 8 + rr;
            const float* mr = g_mem + (size_t)(b * 64 + s) * 256 + lane * 8;
            float4 m0 = __ldcg((const float4*)mr), m1 = __ldcg((const float4*)(mr + 4));
            float4 q0 = *(const float4*)&dvec[lane * 8], q1 = *(const float4*)&dvec[lane * 8 + 4];
            float p = m0.x * q0.x;
            p = fmaf(m0.y, q0.y, p); p = fmaf(m0.z, q0.z, p); p = fmaf(m0.w, q0.w, p);
            p = fmaf(m1.x, q1.x, p); p = fmaf(m1.y, q1.y, p);
            p = fmaf(m1.z, q1.z, p); p = fmaf(m1.w, q1.w, p);
            #pragma unroll
            for (int off = 16; off; off >>= 1) p += __shfl_xor_sync(0xffffffffu, p, off);
            if (lane == 0) sSco[s] = p;
        }
        __syncthreads();
        if (tid < 64) sSco[tid] = -sSco[tid] * sScl[tid] + 0.2f * g_usage[t & 1][b * 64 + tid];
        __syncthreads();
        if (tid < 32) {   // full warp 0: softmax over 64
            float x0 = sSco[tid], x1 = sSco[tid + 32];
            float mx = fmaxf(x0, x1);
            #pragma unroll
            for (int off = 16; off; off >>= 1) mx = fmaxf(mx, __shfl_xor_sync(0xffffffffu, mx, off));
            float e0 = expf(x0 - mx), e1 = expf(x1 - mx);
            float ssum = e0 + e1;
            #pragma unroll
            for (int off = 16; off; off >>= 1) ssum += __shfl_xor_sync(0xffffffffu, ssum, off);
            float inv = 1.f / ssum;
            sSco[tid] = e0 * inv; sSco[tid + 32] = e1 * inv;
        }
        __syncthreads();
        if (tid < 64) {
            float w_ = sSco[tid];
            g_ww[b * 64 + tid] = w_;
            g_usage[(t + 1) & 1][b * 64 + tid] =
                (g_usage[t & 1][b * 64 + tid] + (w_ > 0.01f ? w_ : 0.f)) * 0.99f;
        }
    }
    __syncthreads();

    // HMMA GEMM: 64 x 128 tile (8 warps = 4 row-blocks x 2 col-blocks of 64)
    float acc[8][4] = {};
    mma_gemm<8>(sm, 67584, 135168, acc, wid & 3, wid >> 2, g, q);

    // epilogue
    const int wr = wid & 3, wc = wid >> 2;
    const int row0 = wr * 16 + g, row1 = row0 + 8;
    const int grow0 = b * 64 + row0, grow1 = b * 64 + row1;
    const float* vpb = g_vproj + ((size_t)(b * T_ + t)) * 768;
    if (j < 2) {   // r gate -> rm bf16 hi/lo
        float s0 = sScl[row0], s1 = sScl[row1];
        #pragma unroll
        for (int nt = 0; nt < 8; nt++) {
            int rc = j * 128 + wc * 64 + nt * 8 + 2 * q;
            float2 vp = *(const float2*)(vpb + rc);
            float2 m0 = __ldcg((const float2*)(g_mem + (size_t)grow0 * 256 + rc));
            float2 m1 = __ldcg((const float2*)(g_mem + (size_t)grow1 * 256 + rc));
            float r00 = sigm(acc[nt][0] + vp.x) * (m0.x * s0);
            float r01 = sigm(acc[nt][1] + vp.y) * (m0.y * s0);
            float r10 = sigm(acc[nt][2] + vp.x) * (m1.x * s1);
            float r11 = sigm(acc[nt][3] + vp.y) * (m1.y * s1);
            uint32_t h, l;
            hilo2(r00, r01, h, l);
            *(uint32_t*)((char*)g_rm_h + ((size_t)grow0 * 256 + rc) * 2) = h;
            *(uint32_t*)((char*)g_rm_l + ((size_t)grow0 * 256 + rc) * 2) = l;
            hilo2(r10, r11, h, l);
            *(uint32_t*)((char*)g_rm_h + ((size_t)grow1 * 256 + rc) * 2) = h;
            *(uint32_t*)((char*)g_rm_l + ((size_t)grow1 * 256 + rc) * 2) = l;
        }
    } else {       // z gate -> fp32
        #pragma unroll
        for (int nt = 0; nt < 8; nt++) {
            int zc = (j - 2) * 128 + wc * 64 + nt * 8 + 2 * q;
            float2 vp = *(const float2*)(vpb + 256 + zc);
            float2 o0, o1;
            o0.x = sigm(acc[nt][0] + vp.x); o0.y = sigm(acc[nt][1] + vp.y);
            o1.x = sigm(acc[nt][2] + vp.x); o1.y = sigm(acc[nt][3] + vp.y);
            *(float2*)(g_zg + (size_t)grow0 * 256 + zc) = o0;
            *(float2*)(g_zg + (size_t)grow1 * 256 + zc) = o1;
        }
    }
}

// ---------------- step3: cand HMMA GEMM + masked blend + ss (grid 32*4, N=64 each) ----------------
// smem: AH 0 | AL 33792 | BH 67584 (33792) | BL 101376 | X 135168: sScl 256B, ssbuf 512B
#define S3_X 135168
#define S3_SMEM (S3_X + 768)
__global__ void __launch_bounds__(256) k_step3(int t)
{
    extern __shared__ __align__(16) char sm[];
    const int tid = threadIdx.x, wid = tid >> 5, lane = tid & 31;
    const int g = lane >> 2, q = lane & 3;
    const int b = blockIdx.x >> 2, j = blockIdx.x & 3;
    float* sScl  = (float*)(sm + S3_X);
    float* ssbuf = (float*)(sm + S3_X + 256);   // [2][64]

    if (tid < 64) {
        const float* ssB = g_ss + b * 256;
        float tot = ssB[tid] + ssB[64 + tid] + ssB[128 + tid] + ssB[192 + tid];
        sScl[tid] = 1.f / fmaxf(sqrtf(tot), 1e-12f);
    }

    // A: rm bf16 hi/lo straight copy
    {
        int row = tid >> 2, ks = (tid & 3) * 64;
        const char* shp = (const char*)g_rm_h + ((size_t)(b * 64 + row) * 256 + ks) * 2;
        const char* slp = (const char*)g_rm_l + ((size_t)(b * 64 + row) * 256 + ks) * 2;
        char* dh = sm + row * ST + ks * 2;
        char* dl = dh + 33792;
        #pragma unroll
        for (int i = 0; i < 8; i++) {
            *(uint4*)(dh + i * 16) = __ldcg((const uint4*)(shp + i * 16));
            *(uint4*)(dl + i * 16) = __ldcg((const uint4*)(slp + i * 16));
        }
    }
    // B: Wu slice rows 512 + j*64 .. +63
    {
        int row = tid >> 2, ks = (tid & 3) * 64;
        const char* shp = (const char*)g_Whh + ((size_t)(512 + j * 64 + row) * 256 + ks) * 2;
        const char* slp = (const char*)g_Whl + ((size_t)(512 + j * 64 + row) * 256 + ks) * 2;
        char* dh = sm + 67584 + row * ST + ks * 2;
        char* dl = sm + 101376 + row * ST + ks * 2;
        #pragma unroll
        for (int i = 0; i < 8; i++) {
            *(uint4*)(dh + i * 16) = __ldcg((const uint4*)(shp + i * 16));
            *(uint4*)(dl + i * 16) = __ldcg((const uint4*)(slp + i * 16));
        }
    }
    __syncthreads();

    // HMMA GEMM: 64 x 64 tile (8 warps = 4 row-blocks x 2 col-blocks of 32)
    float acc[4][4] = {};
    mma_gemm<4>(sm, 67584, 101376, acc, wid & 3, wid >> 2, g, q);

    // epilogue: tanh + masked blend (in place) + ss partials
    const int wr = wid & 3, wc = wid >> 2;
    const int row0 = wr * 16 + g, row1 = row0 + 8;
    const int grow0 = b * 64 + row0, grow1 = b * 64 + row1;
    const float* vpb = g_vproj + ((size_t)(b * T_ + t)) * 768 + 512;
    float s0 = sScl[row0], s1 = sScl[row1];
    float ww0 = g_ww[grow0], ww1 = g_ww[grow1];
    bool ok0 = ww0 > 0.01f, ok1 = ww1 > 0.01f;
    float w0 = ww0 * 0.5f, w1 = ww1 * 0.5f;
    float ssum0 = 0.f, ssum1 = 0.f;
    #pragma unroll
    for (int nt = 0; nt < 4; nt++) {
        int uc = j * 64 + wc * 32 + nt * 8 + 2 * q;
        float2 vp = *(const float2*)(vpb + uc);
        float2 z0 = __ldcg((const float2*)(g_zg + (size_t)grow0 * 256 + uc));
        float2 z1 = __ldcg((const float2*)(g_zg + (size_t)grow1 * 256 + uc));
        float2 m0 = __ldcg((const float2*)(g_mem + (size_t)grow0 * 256 + uc));
        float2 m1 = __ldcg((const float2*)(g_mem + (size_t)grow1 * 256 + uc));
        float mv00 = m0.x * s0, mv01 = m0.y * s0;
        float mv10 = m1.x * s1, mv11 = m1.y * s1;
        float c00 = tanhf(acc[nt][0] + vp.x), c01 = tanhf(acc[nt][1] + vp.y);
        float c10 = tanhf(acc[nt][2] + vp.x), c11 = tanhf(acc[nt][3] + vp.y);
        float nh00 = (1.f - z0.x) * mv00 + z0.x * c00;
        float nh01 = (1.f - z0.y) * mv01 + z0.y * c01;
        float nh10 = (1.f - z1.x) * mv10 + z1.x * c10;
        float nh11 = (1.f - z1.y) * mv11 + z1.y * c11;
        float2 o0, o1;
        o0.x = mv00 * (1.f - w0) + nh00 * w0;
        o0.y = mv01 * (1.f - w0) + nh01 * w0;
        o1.x = mv10 * (1.f - w1) + nh10 * w1;
        o1.y = mv11 * (1.f - w1) + nh11 * w1;
        ssum0 = fmaf(o0.x, o0.x, fmaf(o0.y, o0.y, ssum0));
        ssum1 = fmaf(o1.x, o1.x, fmaf(o1.y, o1.y, ssum1));
        if (ok0) *(float2*)(g_mem + (size_t)grow0 * 256 + uc) = o0;
        if (ok1) *(float2*)(g_mem + (size_t)grow1 * 256 + uc) = o1;
    }
    // UNCONDITIONAL shuffles (xor<=2 combines the q-quad only)
    ssum0 += __shfl_xor_sync(0xffffffffu, ssum0, 1);
    ssum0 += __shfl_xor_sync(0xffffffffu, ssum0, 2);
    ssum1 += __shfl_xor_sync(0xffffffffu, ssum1, 1);
    ssum1 += __shfl_xor_sync(0xffffffffu, ssum1, 2);
    if (q == 0) {
        ssbuf[wc * 64 + row0] = ssum0;
        ssbuf[wc * 64 + row1] = ssum1;
    }
    __syncthreads();
    if (tid < 64) {
        int grow = b * 64 + tid;
        if (g_ww[grow] > 0.01f)
            g_ss[(b * 4 + j) * 64 + tid] = ssbuf[tid] + ssbuf[64 + tid];
    }
}

// ---------------- final normalize ----------------
__global__ void k_fin(float* __restrict__ out)
{
    int row = blockIdx.x, tid = threadIdx.x;
    __shared__ float sc;
    if (tid == 0) {
        int b = row >> 6, s = row & 63;
        const float* ssB = g_ss + b * 256;
        float tot = ssB[s] + ssB[64 + s] + ssB[128 + s] + ssB[192 + s];
        sc = 1.f / fmaxf(sqrtf(tot), 1e-12f);
    }
    __syncthreads();
    out[(size_t)row * M_ + tid] = g_mem[(size_t)row * M_ + tid] * sc;
}

// ---------------- launch ----------------
extern "C" void kernel_launch(void* const* d_in, const int* in_sizes, int n_in,
                              void* d_out, int out_size)
{
    const float* hidden  = (const float*)d_in[0];
    const float* meminit = (const float*)d_in[1];
    const float* Wi = (const float*)d_in[2];
    const float* bi = (const float*)d_in[3];
    const float* Wv = (const float*)d_in[4];
    const float* bv = (const float*)d_in[5];
    const float* Wr = (const float*)d_in[6];
    const float* br = (const float*)d_in[7];
    const float* Wz = (const float*)d_in[8];
    const float* bz = (const float*)d_in[9];
    const float* Wu = (const float*)d_in[10];
    const float* bu = (const float*)d_in[11];

    static int attr_done = 0;
    if (!attr_done) {
        cudaFuncSetAttribute(k_step2, cudaFuncAttributeMaxDynamicSharedMemorySize, S2_SMEM);
        cudaFuncSetAttribute(k_step3, cudaFuncAttributeMaxDynamicSharedMemorySize, S3_SMEM);
        attr_done = 1;
    }

    k_pack<<<2048, 256>>>(Wi, bi, Wv, bv, Wr, br, Wz, bz, Wu, bu);
    k_init<<<ROWS_, 256>>>(meminit);
    k_gemm_pre<<<128 * 8, 256>>>(hidden, 0);
    k_gemm_pre<<<128 * 12, 256>>>(hidden, 1);

    for (int t = 0; t < T_; t++) {
        k_step2<<<128, 256, S2_SMEM>>>(t);
        k_step3<<<128, 256, S3_SMEM>>>(t);
    }
    k_fin<<<ROWS_, 256>>>((float*)d_out);
}

// round 15
// speedup vs baseline: 1.0178x; 1.0178x over previous
#include <cuda_runtime.h>
#include <cuda_bf16.h>
#include <math.h>
#include <stdint.h>

#define B_  32
#define T_  256
#define D_  1024
#define M_  256
#define S_  64
#define ROWS_ 2048
#define BT_  8192
#define ST  528               // smem tile row stride (bytes) — conflict-free frag loads
#define NCTA 128u

// ---------------- static device scratch ----------------
__device__ float g_mem[(size_t)ROWS_ * M_];      // raw (pre-norm) memory, in place
__device__ float g_ss[B_ * 4 * S_];              // sum-of-squares partials [b][p][s]
__device__ float g_usage[2][ROWS_];              // parity double-buffered usage
__device__ __nv_bfloat16 g_rm_h[(size_t)ROWS_ * M_];
__device__ __nv_bfloat16 g_rm_l[(size_t)ROWS_ * M_];
__device__ float g_zg[(size_t)ROWS_ * M_];
__device__ float g_mv[(size_t)BT_ * 512];        // mem_input | vals
__device__ float g_vproj[(size_t)BT_ * 768];
__device__ float g_Wiv[(size_t)512 * D_];
__device__ float g_biv[512];
__device__ float g_Wx[(size_t)768 * M_];
__device__ __nv_bfloat16 g_Whh[(size_t)768 * M_];   // h-half weights bf16 hi [n][k]
__device__ __nv_bfloat16 g_Whl[(size_t)768 * M_];   // h-half weights bf16 lo
__device__ float g_bx[768];
__device__ unsigned g_bar[2 * T_];               // one-shot barrier counters (zeroed per launch)

__device__ __forceinline__ float sigm(float x) { return 1.f / (1.f + expf(-x)); }

__device__ __forceinline__ void hilo2(float x0, float x1, uint32_t& hw, uint32_t& lw)
{
    __nv_bfloat162 h, l;
    h.x = __float2bfloat16(x0); h.y = __float2bfloat16(x1);
    l.x = __float2bfloat16(x0 - __bfloat162float(h.x));
    l.y = __float2bfloat16(x1 - __bfloat162float(h.y));
    hw = *(uint32_t*)&h; lw = *(uint32_t*)&l;
}

#define MMA(acc, a0,a1,a2,a3, b0,b1) \
    asm volatile("mma.sync.aligned.m16n8k16.row.col.f32.bf16.bf16.f32 " \
        "{%0,%1,%2,%3}, {%4,%5,%6,%7}, {%8,%9}, {%0,%1,%2,%3};" \
        : "+f"((acc)[0]), "+f"((acc)[1]), "+f"((acc)[2]), "+f"((acc)[3]) \
        : "r"(a0), "r"(a1), "r"(a2), "r"(a3), "r"(b0), "r"(b1))

// grid-wide software barrier with release/acquire ordering.
// Writer: every thread fences its own (stcg) writes, then one arrival atomic.
// Reader: acquire spin + post-release __threadfence() by ALL threads so no
// subsequent load can merge with a pre-barrier in-flight request (stale MSHR).
__device__ __forceinline__ void grid_bar(unsigned* ctr)
{
    __threadfence();
    __syncthreads();
    if (threadIdx.x == 0) {
        atomicAdd(ctr, 1u);
        unsigned v;
        do {
            asm volatile("ld.acquire.gpu.global.u32 %0, [%1];" : "=r"(v) : "l"(ctr) : "memory");
        } while (v < NCTA);
    }
    __syncthreads();
    __threadfence();
}

// ---------------- pack ----------------
__global__ void k_pack(const float* __restrict__ Wi, const float* __restrict__ bi,
                       const float* __restrict__ Wv, const float* __restrict__ bv,
                       const float* __restrict__ Wr, const float* __restrict__ br,
                       const float* __restrict__ Wz, const float* __restrict__ bz,
                       const float* __restrict__ Wu, const float* __restrict__ bu)
{
    int idx = blockIdx.x * blockDim.x + threadIdx.x;
    if (idx < 512 * 1024) {
        int r = idx >> 10, k = idx & 1023;
        g_Wiv[idx] = (r < 256) ? Wi[r * 1024 + k] : Wv[(r - 256) * 1024 + k];
    }
    if (idx < 768 * 256) {
        int n = idx >> 8, k = idx & 255;
        int gate = n >> 8, jj = n & 255;
        const float* Wg = (gate == 0) ? Wr : ((gate == 1) ? Wz : Wu);
        g_Wx[idx] = Wg[jj * 512 + k];
        float w = Wg[jj * 512 + 256 + k];
        __nv_bfloat16 h = __float2bfloat16(w);
        g_Whh[idx] = h;
        g_Whl[idx] = __float2bfloat16(w - __bfloat162float(h));
    }
    if (idx < 768) g_bx[idx] = (idx < 256) ? br[idx] : ((idx < 512) ? bz[idx - 256] : bu[idx - 512]);
    if (idx < 512) g_biv[idx] = (idx < 256) ? bi[idx] : bv[idx - 256];
}

// ---------------- init: mem, ss, usage, barrier counters ----------------
__global__ void k_init(const float* __restrict__ mi)
{
    int row = blockIdx.x, tid = threadIdx.x;
    float v = 0.01f * mi[(size_t)row * M_ + tid];
    g_mem[(size_t)row * M_ + tid] = v;
    float ss = v * v;
    #pragma unroll
    for (int off = 16; off; off >>= 1) ss += __shfl_xor_sync(0xffffffffu, ss, off);
    __shared__ float wsum[8];
    if ((tid & 31) == 0) wsum[tid >> 5] = ss;
    __syncthreads();
    if (tid < 4) {
        int b = row >> 6, s = row & 63;
        g_ss[(b * 4 + tid) * 64 + s] = wsum[2 * tid] + wsum[2 * tid + 1];
    }
    if (tid == 0) g_usage[0][row] = 0.f;
    if (row == 0) { g_bar[tid] = 0u; g_bar[256 + tid] = 0u; }   // zero all 512 counters
}

// ---------------- precompute GEMMs (fp32, unchanged/passing) ----------------
template<int KTILE>
__device__ __forceinline__ void gemm_tile(const float* __restrict__ A, int lda,
                                          const float* __restrict__ W, int ldw,
                                          int K, int row0, int n0, float acc[4][4])
{
    __shared__ __align__(16) float sA[KTILE][68];
    __shared__ __align__(16) float sW[KTILE][68];
    const int tid = threadIdx.x;
    const int lr = tid >> 2, lk = (tid & 3) * 4;
    const int ty = tid >> 4, tx = tid & 15;
    for (int k0 = 0; k0 < K; k0 += KTILE) {
        float4 av = *(const float4*)(A + (size_t)(row0 + lr) * lda + k0 + lk);
        float4 wv = *(const float4*)(W + (size_t)(n0 + lr) * ldw + k0 + lk);
        __syncthreads();
        sA[lk + 0][lr] = av.x; sA[lk + 1][lr] = av.y; sA[lk + 2][lr] = av.z; sA[lk + 3][lr] = av.w;
        sW[lk + 0][lr] = wv.x; sW[lk + 1][lr] = wv.y; sW[lk + 2][lr] = wv.z; sW[lk + 3][lr] = wv.w;
        __syncthreads();
        #pragma unroll
        for (int kk = 0; kk < KTILE; kk++) {
            float4 a = *(const float4*)&sA[kk][ty * 4];
            float4 w = *(const float4*)&sW[kk][tx * 4];
            float ar[4] = {a.x, a.y, a.z, a.w};
            float wr[4] = {w.x, w.y, w.z, w.w};
            #pragma unroll
            for (int i = 0; i < 4; i++)
                #pragma unroll
                for (int j = 0; j < 4; j++)
                    acc[i][j] = fmaf(ar[i], wr[j], acc[i][j]);
        }
    }
}

__global__ void k_gemm_pre(const float* __restrict__ hidden, int mode)
{
    const float* A; const float* W; const float* bias; float* C;
    int lda, ldw, ldc, K, ntn;
    if (mode == 0) { A = hidden;     lda = 1024; W = g_Wiv; ldw = 1024; bias = g_biv; C = g_mv;    ldc = 512; K = 1024; ntn = 8;  }
    else           { A = g_mv + 256; lda = 512;  W = g_Wx;  ldw = 256;  bias = g_bx;  C = g_vproj; ldc = 768; K = 256;  ntn = 12; }
    int tr = blockIdx.x / ntn, tc = blockIdx.x % ntn;
    int row0 = tr * 64, n0 = tc * 64;
    float acc[4][4] = {};
    gemm_tile<16>(A, lda, W, ldw, K, row0, n0, acc);
    int ty = threadIdx.x >> 4, tx = threadIdx.x & 15;
    #pragma unroll
    for (int i = 0; i < 4; i++) {
        int r = row0 + ty * 4 + i;
        #pragma unroll
        for (int j = 0; j < 4; j++) {
            int n = n0 + tx * 4 + j;
            C[(size_t)r * ldc + n] = acc[i][j] + bias[n];
        }
    }
}

// ---------------- HMMA core (verified in R12): 64 x (NT*8*2) x 256, bf16-split 3-pass ----------------
template<int NT>
__device__ __forceinline__ void mma_gemm(const char* sm, uint32_t bhOff, uint32_t blOff,
                                         float acc[NT][4], int wr, int wc, int g, int q)
{
    const char* pAH = sm + (wr * 16 + g) * ST + q * 4;
    const char* pAL = pAH + 33792;
    const char* pBH = sm + bhOff + (wc * (NT * 8) + g) * ST + q * 4;
    const char* pBL = sm + blOff + (wc * (NT * 8) + g) * ST + q * 4;
    #pragma unroll 2
    for (int kc = 0; kc < 16; kc++) {
        const int kb = kc * 32;
        uint32_t ah0 = *(const uint32_t*)(pAH + kb);
        uint32_t ah1 = *(const uint32_t*)(pAH + kb + 8 * ST);
        uint32_t ah2 = *(const uint32_t*)(pAH + kb + 16);
        uint32_t ah3 = *(const uint32_t*)(pAH + kb + 8 * ST + 16);
        uint32_t al0 = *(const uint32_t*)(pAL + kb);
        uint32_t al1 = *(const uint32_t*)(pAL + kb + 8 * ST);
        uint32_t al2 = *(const uint32_t*)(pAL + kb + 16);
        uint32_t al3 = *(const uint32_t*)(pAL + kb + 8 * ST + 16);
        #pragma unroll
        for (int nt = 0; nt < NT; nt++) {
            uint32_t bh0 = *(const uint32_t*)(pBH + nt * 8 * ST + kb);
            uint32_t bh1 = *(const uint32_t*)(pBH + nt * 8 * ST + kb + 16);
            uint32_t bl0 = *(const uint32_t*)(pBL + nt * 8 * ST + kb);
            uint32_t bl1 = *(const uint32_t*)(pBL + nt * 8 * ST + kb + 16);
            MMA(acc[nt], ah0, ah1, ah2, ah3, bh0, bh1);
            MMA(acc[nt], al0, al1, al2, al3, bh0, bh1);
            MMA(acc[nt], ah0, ah1, ah2, ah3, bl0, bl1);
        }
    }
}

// ---------------- persistent step kernel: grid 128 = 32 batches x 4 slices ----------------
#define PS_X 202752
#define PS_SMEM (PS_X + 2304)
__global__ void __launch_bounds__(256) k_persist()
{
    extern __shared__ __align__(16) char sm[];
    const int tid = threadIdx.x, wid = tid >> 5, lane = tid & 31;
    const int g = lane >> 2, q = lane & 3;
    const int b = blockIdx.x >> 2, j = blockIdx.x & 3;
    float* sScl = (float*)(sm + PS_X);
    float* sSco = (float*)(sm + PS_X + 256);
    float* sWw  = (float*)(sm + PS_X + 512);
    float* dvec = (float*)(sm + PS_X + 768);
    float* ssbuf= (float*)(sm + PS_X + 1792);

    // resident Wrz_h slice j (128 rows) — loaded once
    {
        int row = tid >> 1, ks = (tid & 1) * 128;
        const char* shp = (const char*)g_Whh + ((size_t)(j * 128 + row) * 256 + ks) * 2;
        char* dh = sm + 67584 + row * ST + ks * 2;
        #pragma unroll
        for (int i = 0; i < 16; i++)
            *(uint4*)(dh + i * 16) = *(const uint4*)(shp + i * 16);
    }

    #pragma unroll 1
    for (int t = 0; t < T_; t++) {
        // stream Wrz_l slice -> Bstream
        {
            int row = tid >> 1, ks = (tid & 1) * 128;
            const char* slp = (const char*)g_Whl + ((size_t)(j * 128 + row) * 256 + ks) * 2;
            char* dl = sm + 135168 + row * ST + ks * 2;
            #pragma unroll
            for (int i = 0; i < 16; i++)
                *(uint4*)(dl + i * 16) = *(const uint4*)(slp + i * 16);
        }
        if (tid < 64) {
            const float* ssB = g_ss + b * 256;
            float tot = __ldcg(ssB + tid) + __ldcg(ssB + 64 + tid)
                      + __ldcg(ssB + 128 + tid) + __ldcg(ssB + 192 + tid);
            sScl[tid] = 1.f / fmaxf(sqrtf(tot), 1e-12f);
        }
        dvec[tid] = g_mv[((size_t)(b * T_ + t)) * 512 + tid];
        __syncthreads();

        // A build: mem_norm -> bf16 hi/lo
        {
            int row = tid >> 2, ks = (tid & 3) * 64;
            float scl = sScl[row];
            const float* src = g_mem + (size_t)(b * 64 + row) * 256 + ks;
            char* dh = sm + row * ST + ks * 2;
            char* dl = dh + 33792;
            #pragma unroll
            for (int i = 0; i < 16; i++) {
                float4 f = __ldcg((const float4*)(src + i * 4));
                uint32_t h0, l0, h1, l1;
                hilo2(f.x * scl, f.y * scl, h0, l0);
                hilo2(f.z * scl, f.w * scl, h1, l1);
                *(uint32_t*)(dh + i * 8) = h0; *(uint32_t*)(dh + i * 8 + 4) = h1;
                *(uint32_t*)(dl + i * 8) = l0; *(uint32_t*)(dl + i * 8 + 4) = l1;
            }
        }
        // sim (redundant per CTA; deterministic-identical)
        #pragma unroll
        for (int rr = 0; rr < 8; rr++) {
            int s = wid * 8 + rr;
            const float* mr = g_mem + (size_t)(b * 64 + s) * 256 + lane * 8;
            float4 m0 = __ldcg((const float4*)mr), m1 = __ldcg((const float4*)(mr + 4));
            float4 q0 = *(const float4*)&dvec[lane * 8], q1 = *(const float4*)&dvec[lane * 8 + 4];
            float p = m0.x * q0.x;
            p = fmaf(m0.y, q0.y, p); p = fmaf(m0.z, q0.z, p); p = fmaf(m0.w, q0.w, p);
            p = fmaf(m1.x, q1.x, p); p = fmaf(m1.y, q1.y, p);
            p = fmaf(m1.z, q1.z, p); p = fmaf(m1.w, q1.w, p);
            #pragma unroll
            for (int off = 16; off; off >>= 1) p += __shfl_xor_sync(0xffffffffu, p, off);
            if (lane == 0) sSco[s] = p;
        }
        __syncthreads();
        if (tid < 64) sSco[tid] = -sSco[tid] * sScl[tid] + 0.2f * __ldcg(&g_usage[t & 1][b * 64 + tid]);
        __syncthreads();
        if (tid < 32) {   // full warp 0: softmax over 64
            float x0 = sSco[tid], x1 = sSco[tid + 32];
            float mx = fmaxf(x0, x1);
            #pragma unroll
            for (int off = 16; off; off >>= 1) mx = fmaxf(mx, __shfl_xor_sync(0xffffffffu, mx, off));
            float e0 = expf(x0 - mx), e1 = expf(x1 - mx);
            float ssum = e0 + e1;
            #pragma unroll
            for (int off = 16; off; off >>= 1) ssum += __shfl_xor_sync(0xffffffffu, ssum, off);
            float inv = 1.f / ssum;
            sWw[tid] = e0 * inv; sWw[tid + 32] = e1 * inv;
        }
        __syncthreads();
        if (j == 0 && tid < 64) {
            float w_ = sWw[tid];
            __stcg(&g_usage[(t + 1) & 1][b * 64 + tid],
                   (__ldcg(&g_usage[t & 1][b * 64 + tid]) + (w_ > 0.01f ? w_ : 0.f)) * 0.99f);
        }

        // rz GEMM: 64 x 128 (Bh resident, Bl streamed)
        float acc[8][4] = {};
        mma_gemm<8>(sm, 67584, 135168, acc, wid & 3, wid >> 2, g, q);

        // rz epilogue
        {
            const int wr = wid & 3, wc = wid >> 2;
            const int row0 = wr * 16 + g, row1 = row0 + 8;
            const int grow0 = b * 64 + row0, grow1 = b * 64 + row1;
            const float* vpb = g_vproj + ((size_t)(b * T_ + t)) * 768;
            if (j < 2) {   // r -> rm bf16 hi/lo
                float s0 = sScl[row0], s1 = sScl[row1];
                #pragma unroll
                for (int nt = 0; nt < 8; nt++) {
                    int rc = j * 128 + wc * 64 + nt * 8 + 2 * q;
                    float2 vp = *(const float2*)(vpb + rc);
                    float2 m0 = __ldcg((const float2*)(g_mem + (size_t)grow0 * 256 + rc));
                    float2 m1 = __ldcg((const float2*)(g_mem + (size_t)grow1 * 256 + rc));
                    float r00 = sigm(acc[nt][0] + vp.x) * (m0.x * s0);
                    float r01 = sigm(acc[nt][1] + vp.y) * (m0.y * s0);
                    float r10 = sigm(acc[nt][2] + vp.x) * (m1.x * s1);
                    float r11 = sigm(acc[nt][3] + vp.y) * (m1.y * s1);
                    uint32_t h, l;
                    hilo2(r00, r01, h, l);
                    __stcg((uint32_t*)((char*)g_rm_h + ((size_t)grow0 * 256 + rc) * 2), h);
                    __stcg((uint32_t*)((char*)g_rm_l + ((size_t)grow0 * 256 + rc) * 2), l);
                    hilo2(r10, r11, h, l);
                    __stcg((uint32_t*)((char*)g_rm_h + ((size_t)grow1 * 256 + rc) * 2), h);
                    __stcg((uint32_t*)((char*)g_rm_l + ((size_t)grow1 * 256 + rc) * 2), l);
                }
            } else {       // z -> fp32
                #pragma unroll
                for (int nt = 0; nt < 8; nt++) {
                    int zc = (j - 2) * 128 + wc * 64 + nt * 8 + 2 * q;
                    float2 vp = *(const float2*)(vpb + 256 + zc);
                    float2 o0, o1;
                    o0.x = sigm(acc[nt][0] + vp.x); o0.y = sigm(acc[nt][1] + vp.y);
                    o1.x = sigm(acc[nt][2] + vp.x); o1.y = sigm(acc[nt][3] + vp.y);
                    __stcg((float2*)(g_zg + (size_t)grow0 * 256 + zc), o0);
                    __stcg((float2*)(g_zg + (size_t)grow1 * 256 + zc), o1);
                }
            }
        }
        grid_bar(&g_bar[2 * t]);      // rm/zg visible grid-wide

        // phase 2: A <- rm hi/lo; Bstream <- Wu_h | Wu_l
        {
            int row = tid >> 2, ks = (tid & 3) * 64;
            const char* shp = (const char*)g_rm_h + ((size_t)(b * 64 + row) * 256 + ks) * 2;
            const char* slp = (const char*)g_rm_l + ((size_t)(b * 64 + row) * 256 + ks) * 2;
            char* dh = sm + row * ST + ks * 2;
            char* dl = dh + 33792;
            #pragma unroll
            for (int i = 0; i < 8; i++) {
                *(uint4*)(dh + i * 16) = __ldcg((const uint4*)(shp + i * 16));
                *(uint4*)(dl + i * 16) = __ldcg((const uint4*)(slp + i * 16));
            }
        }
        {
            int row = tid >> 2, ks = (tid & 3) * 64;
            const char* shp = (const char*)g_Whh + ((size_t)(512 + j * 64 + row) * 256 + ks) * 2;
            const char* slp = (const char*)g_Whl + ((size_t)(512 + j * 64 + row) * 256 + ks) * 2;
            char* dh = sm + 135168 + row * ST + ks * 2;
            char* dl = sm + 168960 + row * ST + ks * 2;
            #pragma unroll
            for (int i = 0; i < 8; i++) {
                *(uint4*)(dh + i * 16) = *(const uint4*)(shp + i * 16);
                *(uint4*)(dl + i * 16) = *(const uint4*)(slp + i * 16);
            }
        }
        __syncthreads();

        // u GEMM: 64 x 64
        float acu[4][4] = {};
        mma_gemm<4>(sm, 135168, 168960, acu, wid & 3, wid >> 2, g, q);

        // u epilogue: tanh + masked blend + ss partials
        {
            const int wr = wid & 3, wc = wid >> 2;
            const int row0 = wr * 16 + g, row1 = row0 + 8;
            const int grow0 = b * 64 + row0, grow1 = b * 64 + row1;
            const float* vpb = g_vproj + ((size_t)(b * T_ + t)) * 768 + 512;
            float s0 = sScl[row0], s1 = sScl[row1];
            float ww0 = sWw[row0], ww1 = sWw[row1];
            bool ok0 = ww0 > 0.01f, ok1 = ww1 > 0.01f;
            float w0 = ww0 * 0.5f, w1 = ww1 * 0.5f;
            float ssum0 = 0.f, ssum1 = 0.f;
            #pragma unroll
            for (int nt = 0; nt < 4; nt++) {
                int uc = j * 64 + wc * 32 + nt * 8 + 2 * q;
                float2 vp = *(const float2*)(vpb + uc);
                float2 z0 = __ldcg((const float2*)(g_zg + (size_t)grow0 * 256 + uc));
                float2 z1 = __ldcg((const float2*)(g_zg + (size_t)grow1 * 256 + uc));
                float2 m0 = __ldcg((const float2*)(g_mem + (size_t)grow0 * 256 + uc));
                float2 m1 = __ldcg((const float2*)(g_mem + (size_t)grow1 * 256 + uc));
                float mv00 = m0.x * s0, mv01 = m0.y * s0;
                float mv10 = m1.x * s1, mv11 = m1.y * s1;
                float c00 = tanhf(acu[nt][0] + vp.x), c01 = tanhf(acu[nt][1] + vp.y);
                float c10 = tanhf(acu[nt][2] + vp.x), c11 = tanhf(acu[nt][3] + vp.y);
                float nh00 = (1.f - z0.x) * mv00 + z0.x * c00;
                float nh01 = (1.f - z0.y) * mv01 + z0.y * c01;
                float nh10 = (1.f - z1.x) * mv10 + z1.x * c10;
                float nh11 = (1.f - z1.y) * mv11 + z1.y * c11;
                float2 o0, o1;
                o0.x = mv00 * (1.f - w0) + nh00 * w0;
                o0.y = mv01 * (1.f - w0) + nh01 * w0;
                o1.x = mv10 * (1.f - w1) + nh10 * w1;
                o1.y = mv11 * (1.f - w1) + nh11 * w1;
                ssum0 = fmaf(o0.x, o0.x, fmaf(o0.y, o0.y, ssum0));
                ssum1 = fmaf(o1.x, o1.x, fmaf(o1.y, o1.y, ssum1));
                if (ok0) __stcg((float2*)(g_mem + (size_t)grow0 * 256 + uc), o0);
                if (ok1) __stcg((float2*)(g_mem + (size_t)grow1 * 256 + uc), o1);
            }
            // UNCONDITIONAL shuffles (xor<=2 combines the q-quad only)
            ssum0 += __shfl_xor_sync(0xffffffffu, ssum0, 1);
            ssum0 += __shfl_xor_sync(0xffffffffu, ssum0, 2);
            ssum1 += __shfl_xor_sync(0xffffffffu, ssum1, 1);
            ssum1 += __shfl_xor_sync(0xffffffffu, ssum1, 2);
            if (q == 0) {
                ssbuf[wc * 64 + row0] = ssum0;
                ssbuf[wc * 64 + row1] = ssum1;
            }
        }
        __syncthreads();
        if (tid < 64 && sWw[tid] > 0.01f)
            __stcg(&g_ss[(b * 4 + j) * 64 + tid], ssbuf[tid] + ssbuf[64 + tid]);
        grid_bar(&g_bar[2 * t + 1]);  // mem/ss/usage visible for next step
    }
}

// ---------------- final normalize ----------------
__global__ void k_fin(float* __restrict__ out)
{
    int row = blockIdx.x, tid = threadIdx.x;
    __shared__ float sc;
    if (tid == 0) {
        int b = row >> 6, s = row & 63;
        const float* ssB = g_ss + b * 256;
        float tot = ssB[s] + ssB[64 + s] + ssB[128 + s] + ssB[192 + s];
        sc = 1.f / fmaxf(sqrtf(tot), 1e-12f);
    }
    __syncthreads();
    out[(size_t)row * M_ + tid] = g_mem[(size_t)row * M_ + tid] * sc;
}

// ---------------- launch ----------------
extern "C" void kernel_launch(void* const* d_in, const int* in_sizes, int n_in,
                              void* d_out, int out_size)
{
    const float* hidden  = (const float*)d_in[0];
    const float* meminit = (const float*)d_in[1];
    const float* Wi = (const float*)d_in[2];
    const float* bi = (const float*)d_in[3];
    const float* Wv = (const float*)d_in[4];
    const float* bv = (const float*)d_in[5];
    const float* Wr = (const float*)d_in[6];
    const float* br = (const float*)d_in[7];
    const float* Wz = (const float*)d_in[8];
    const float* bz = (const float*)d_in[9];
    const float* Wu = (const float*)d_in[10];
    const float* bu = (const float*)d_in[11];

    static int attr_done = 0;
    if (!attr_done) {
        cudaFuncSetAttribute(k_persist, cudaFuncAttributeMaxDynamicSharedMemorySize, PS_SMEM);
        attr_done = 1;
    }

    k_pack<<<2048, 256>>>(Wi, bi, Wv, bv, Wr, br, Wz, bz, Wu, bu);
    k_init<<<ROWS_, 256>>>(meminit);
    k_gemm_pre<<<128 * 8, 256>>>(hidden, 0);
    k_gemm_pre<<<128 * 12, 256>>>(hidden, 1);
    k_persist<<<128, 256, PS_SMEM>>>();
    k_fin<<<ROWS_, 256>>>((float*)d_out);
}